// round 17
// baseline (speedup 1.0000x reference)
#include <cuda_runtime.h>
#include <cstdint>

#define NNODES 10000
#define FDIM   256
#define DDIM   512
#define NEDGE  160000
#define NHEAD  8
#define SEMH   128
#define OSZ    64

// ---------------- scratch (static device globals; no allocation) ----------------
__device__ float g_feat[4][NNODES * DDIM];
__device__ float g_z   [4][NNODES * DDIM];
__device__ int   g_off [4][NNODES + 1];
__device__ int   g_eid [4][NEDGE];

// one contiguous zero-initialized accumulator region (single memset)
#define ZW_CUR 0
#define ZW_EL  (4 * NNODES)
#define ZW_ER  (ZW_EL + 4 * NNODES * NHEAD)
#define ZW_W   (ZW_ER + 4 * NNODES * NHEAD)
#define ZW_TOT (ZW_W + 4 * NNODES)
__device__ unsigned g_zbuf[ZW_TOT];
#define G_CUR(z) ((int*)g_zbuf + (z) * NNODES)
#define G_EL(z)  ((float*)g_zbuf + ZW_EL + (z) * NNODES * NHEAD)
#define G_ER(z)  ((float*)g_zbuf + ZW_ER + (z) * NNODES * NHEAD)
#define G_W(z)   ((float*)g_zbuf + ZW_W + (z) * NNODES)

// tf32-at-rest operands (bits stored as unsigned)
__device__ unsigned t_x   [2][NNODES * FDIM];
__device__ unsigned t_whw [2][FDIM * FDIM];
__device__ unsigned t_fc  [2][2 * FDIM * DDIM];
__device__ unsigned t_pred[2][DDIM * OSZ];
__device__ unsigned t_W1  [2][DDIM * SEMH];
__device__ unsigned t_W   [4][FDIM * DDIM];
__device__ unsigned t_z   [4][NNODES * DDIM];
__device__ unsigned t_h   [2][NNODES * OSZ];

struct GB {
    const void* A[4]; const void* B[4]; void* C[4]; void* C2[4];
    const float* AL[4]; const float* AR[4]; float* EL[4]; float* ER[4];
    const float* B1[4]; const float* W2p[4]; float* WO[4];
};
struct PG {
    const float* z0[2]; const float* z1[2]; const float* w0[2]; const float* w1[2];
    const unsigned* B[2]; float* C[2]; unsigned* C2[2];
};
struct IP4  { const int*   p[4]; };
struct FP4  { const float* p[4]; };
struct CVT  { const float* src[10]; unsigned* dst[10]; int n4[10]; };

__device__ __forceinline__ unsigned f2tf(float f) {
    unsigned r;
    asm("cvt.rna.tf32.f32 %0, %1;" : "=r"(r) : "f"(f));
    return r;
}

// ---------------- one-shot f32 -> tf32 conversion ----------
__global__ void cvt_kernel(CVT c) {
    int seg = blockIdx.y;
    int n4 = c.n4[seg];
    const float4* s = (const float4*)c.src[seg];
    uint4* d = (uint4*)c.dst[seg];
    for (int i = blockIdx.x * 256 + threadIdx.x; i < n4; i += gridDim.x * 256) {
        float4 v = s[i];
        d[i] = make_uint4(f2tf(v.x), f2tf(v.y), f2tf(v.z), f2tf(v.w));
    }
}

// ---------------- async tf32 MMA GEMM: cp.async 4-stage, z-batched -----------
// EPI: 0 f32 C; 1 tf32 C; 2 f32 C + tf32 C2; 3 f32 streaming;
//      4 f32 C + fused el/er; 5 fused semantic score (no C store).

template<int MT, bool TRANSB, int EPI>
__global__ __launch_bounds__(256, 2) void mma_gemm_async(GB gb, int M, int N, int K) {
    constexpr int S  = 4;
    constexpr int BM = 32 * MT;
    constexpr int PA = 20;
    constexpr int PB = TRANSB ? 20 : 136;
    constexpr int AW = BM * PA;
    constexpr int BW = TRANSB ? 128 * PB : 16 * PB;
    constexpr int AQ = BM / 64;
    extern __shared__ unsigned smem[];

    const unsigned* __restrict__ A = (const unsigned*)gb.A[blockIdx.z];
    const unsigned* __restrict__ B = (const unsigned*)gb.B[blockIdx.z];
    float* C = (float*)gb.C[blockIdx.z];
    unsigned* C2 = (unsigned*)gb.C2[blockIdx.z];

    int tid = threadIdx.x, warp = tid >> 5, lane = tid & 31;
    int wm = warp >> 2, wn = warp & 3;
    int row0 = blockIdx.y * BM, col0 = blockIdx.x * 128;
    int nk = K >> 4;
    unsigned sbase = (unsigned)__cvta_generic_to_shared(smem);

    auto issue = [&](int t) {
        int k0 = t * 16, buf = t & (S - 1);
#pragma unroll
        for (int j = 0; j < AQ; j++) {
            int i = tid + j * 256;
            int r = i >> 2, c4 = i & 3;
            int gr = row0 + r;
            int sz = 16;
            if (gr >= M) { sz = 0; gr = row0; }
            unsigned sd = sbase + ((buf * AW + r * PA + c4 * 4) << 2);
            asm volatile("cp.async.cg.shared.global [%0], [%1], 16, %2;"
                         :: "r"(sd), "l"(A + (size_t)gr * K + k0 + c4 * 4), "r"(sz));
        }
#pragma unroll
        for (int j = 0; j < 2; j++) {
            int i = tid + j * 256;
            const unsigned* src;
            int dstw, sz = 16;
            if (!TRANSB) {
                int k = i >> 5, c4 = i & 31;
                int gc = col0 + c4 * 4;
                if (gc >= N) { sz = 0; gc = col0; }
                src = B + (size_t)(k0 + k) * N + gc;
                dstw = k * PB + c4 * 4;
            } else {
                int n = i >> 2, c4 = i & 3;
                int gn = col0 + n;
                if (gn >= N) { sz = 0; gn = col0; }
                src = B + (size_t)gn * K + k0 + c4 * 4;
                dstw = n * PB + c4 * 4;
            }
            unsigned sd = sbase + ((S * AW + buf * BW + dstw) << 2);
            asm volatile("cp.async.cg.shared.global [%0], [%1], 16, %2;"
                         :: "r"(sd), "l"(src), "r"(sz));
        }
    };

    float acc[MT][4][4];
#pragma unroll
    for (int i = 0; i < MT; i++)
#pragma unroll
        for (int j = 0; j < 4; j++)
#pragma unroll
            for (int q = 0; q < 4; q++) acc[i][j][q] = 0.f;

#pragma unroll
    for (int t = 0; t < S - 1; t++) {
        if (t < nk) issue(t);
        asm volatile("cp.async.commit_group;");
    }

    const unsigned aLdm = ((wm * MT * 16 + (lane & 15)) * PA + (lane >> 4) * 4) << 2;
    const unsigned bLdm = TRANSB
        ? (((wn * 32 + (lane & 7) + ((lane >> 4) & 1) * 8) * PB + ((lane >> 3) & 1) * 4) << 2)
        : 0u;
    const int bB0 = (lane & 3) * PB + wn * 32 + (lane >> 2);

    for (int t = 0; t < nk; t++) {
        int buf = t & (S - 1);
        asm volatile("cp.async.wait_group %0;" :: "n"(S - 2));
        __syncthreads();
        if (t + S - 1 < nk) issue(t + S - 1);
        asm volatile("cp.async.commit_group;");

#pragma unroll
        for (int ks = 0; ks < 2; ks++) {
            unsigned af[MT][4];
            unsigned bf[4][2];
            unsigned aAddr = sbase + ((buf * AW) << 2) + aLdm + ((ks * 8) << 2);
#pragma unroll
            for (int mt = 0; mt < MT; mt++) {
                asm volatile("ldmatrix.sync.aligned.m8n8.x4.shared.b16 "
                             "{%0,%1,%2,%3}, [%4];"
                             : "=r"(af[mt][0]), "=r"(af[mt][1]),
                               "=r"(af[mt][2]), "=r"(af[mt][3])
                             : "r"(aAddr + ((mt * 16 * PA) << 2)));
            }
            if (TRANSB) {
                unsigned bAddr = sbase + ((S * AW + buf * BW) << 2) + bLdm + ((ks * 8) << 2);
#pragma unroll
                for (int p = 0; p < 2; p++) {
                    asm volatile("ldmatrix.sync.aligned.m8n8.x4.shared.b16 "
                                 "{%0,%1,%2,%3}, [%4];"
                                 : "=r"(bf[2 * p][0]), "=r"(bf[2 * p][1]),
                                   "=r"(bf[2 * p + 1][0]), "=r"(bf[2 * p + 1][1])
                                 : "r"(bAddr + ((p * 16 * PB) << 2)));
                }
            } else {
                const unsigned* bp = smem + S * AW + buf * BW + bB0;
#pragma unroll
                for (int nt = 0; nt < 4; nt++) {
                    const unsigned* p = bp + ks * 8 * PB + nt * 8;
                    bf[nt][0] = p[0];
                    bf[nt][1] = p[4 * PB];
                }
            }
#pragma unroll
            for (int mt = 0; mt < MT; mt++)
#pragma unroll
                for (int nt = 0; nt < 4; nt++) {
                    asm volatile(
                        "mma.sync.aligned.m16n8k8.row.col.f32.tf32.tf32.f32 "
                        "{%0,%1,%2,%3}, {%4,%5,%6,%7}, {%8,%9}, {%0,%1,%2,%3};"
                        : "+f"(acc[mt][nt][0]), "+f"(acc[mt][nt][1]),
                          "+f"(acc[mt][nt][2]), "+f"(acc[mt][nt][3])
                        : "r"(af[mt][0]), "r"(af[mt][1]), "r"(af[mt][2]), "r"(af[mt][3]),
                          "r"(bf[nt][0]), "r"(bf[nt][1]));
                }
        }
    }

    // ---------------- epilogue ----------------
    if (EPI != 5) {
#pragma unroll
        for (int mt = 0; mt < MT; mt++) {
            int r0 = row0 + wm * (MT * 16) + mt * 16 + (lane >> 2);
#pragma unroll
            for (int nt = 0; nt < 4; nt++) {
                int c = col0 + wn * 32 + nt * 8 + (lane & 3) * 2;
                if (c < N) {
#pragma unroll
                    for (int h = 0; h < 2; h++) {
                        int r = r0 + h * 8;
                        if (r < M) {
                            float v0 = acc[mt][nt][2 * h], v1 = acc[mt][nt][2 * h + 1];
                            if (EPI == 0 || EPI == 2 || EPI == 4)
                                *(float2*)(C + (size_t)r * N + c) = make_float2(v0, v1);
                            if (EPI == 3)
                                asm volatile("st.global.cs.v2.f32 [%0], {%1,%2};"
                                             :: "l"(C + (size_t)r * N + c), "f"(v0), "f"(v1)
                                             : "memory");
                            if (EPI == 1)
                                *(uint2*)((unsigned*)C + (size_t)r * N + c) =
                                    make_uint2(f2tf(v0), f2tf(v1));
                            if (EPI == 2)
                                *(uint2*)(C2 + (size_t)r * N + c) =
                                    make_uint2(f2tf(v0), f2tf(v1));
                        }
                    }
                }
            }
        }
    }
    if (EPI == 4) {
        int head = (col0 >> 6) + (wn >> 1);
        const float* al = gb.AL[blockIdx.z] + head * 64;
        const float* ar = gb.AR[blockIdx.z] + head * 64;
        float alv[4][2], arv[4][2];
#pragma unroll
        for (int nt = 0; nt < 4; nt++) {
            int cc = (wn & 1) * 32 + nt * 8 + (lane & 3) * 2;
            alv[nt][0] = al[cc];     alv[nt][1] = al[cc + 1];
            arv[nt][0] = ar[cc];     arv[nt][1] = ar[cc + 1];
        }
        float* ELp = gb.EL[blockIdx.z];
        float* ERp = gb.ER[blockIdx.z];
#pragma unroll
        for (int mt = 0; mt < MT; mt++) {
            int r0 = row0 + wm * (MT * 16) + mt * 16 + (lane >> 2);
#pragma unroll
            for (int h = 0; h < 2; h++) {
                float ep = 0.f, rp = 0.f;
#pragma unroll
                for (int nt = 0; nt < 4; nt++) {
                    ep += acc[mt][nt][2 * h] * alv[nt][0] + acc[mt][nt][2 * h + 1] * alv[nt][1];
                    rp += acc[mt][nt][2 * h] * arv[nt][0] + acc[mt][nt][2 * h + 1] * arv[nt][1];
                }
                ep += __shfl_xor_sync(0xffffffffu, ep, 1);
                ep += __shfl_xor_sync(0xffffffffu, ep, 2);
                rp += __shfl_xor_sync(0xffffffffu, rp, 1);
                rp += __shfl_xor_sync(0xffffffffu, rp, 2);
                int r = r0 + h * 8;
                if ((lane & 3) == 0 && r < M) {
                    atomicAdd(&ELp[r * NHEAD + head], ep);
                    atomicAdd(&ERp[r * NHEAD + head], rp);
                }
            }
        }
    }
    if (EPI == 5) {
        const float* b1 = gb.B1[blockIdx.z];
        const float* W2 = gb.W2p[blockIdx.z];
        float b1v[4][2], w2v[4][2];
#pragma unroll
        for (int nt = 0; nt < 4; nt++) {
            int cc = wn * 32 + nt * 8 + (lane & 3) * 2;
            b1v[nt][0] = b1[cc];     b1v[nt][1] = b1[cc + 1];
            w2v[nt][0] = W2[cc];     w2v[nt][1] = W2[cc + 1];
        }
        float* wout = gb.WO[blockIdx.z];
#pragma unroll
        for (int mt = 0; mt < MT; mt++) {
            int r0 = row0 + wm * (MT * 16) + mt * 16 + (lane >> 2);
#pragma unroll
            for (int h = 0; h < 2; h++) {
                float s = 0.f;
#pragma unroll
                for (int nt = 0; nt < 4; nt++) {
                    s += tanhf(acc[mt][nt][2 * h]     + b1v[nt][0]) * w2v[nt][0];
                    s += tanhf(acc[mt][nt][2 * h + 1] + b1v[nt][1]) * w2v[nt][1];
                }
                s += __shfl_xor_sync(0xffffffffu, s, 1);
                s += __shfl_xor_sync(0xffffffffu, s, 2);
                int r = r0 + h * 8;
                if ((lane & 3) == 0 && r < M) atomicAdd(&wout[r], s);
            }
        }
    }
}

// ---------------- pred GEMM with fused metapath fusion in A-staging ----------
__global__ __launch_bounds__(256, 2) void pred_fused_kernel(PG pg, int M, int N, int K) {
    constexpr int PA = 20;
    constexpr int PB = 136;
    __shared__ unsigned sA[2][64 * PA];
    __shared__ unsigned sB[2][16 * PB];
    __shared__ float sbe[64];

    int b = blockIdx.z;
    const float* __restrict__ Z0 = pg.z0[b];
    const float* __restrict__ Z1 = pg.z1[b];
    const unsigned* __restrict__ B = pg.B[b];
    float* C = pg.C[b];
    unsigned* C2 = pg.C2[b];

    int tid = threadIdx.x, warp = tid >> 5, lane = tid & 31;
    int wm = warp >> 2, wn = warp & 3;
    int row0 = blockIdx.y * 64, col0 = 0;
    int nk = K >> 4;

    if (tid < 64) {
        int r = row0 + tid;
        float be = 0.f;
        if (r < M) {
            float a = pg.w0[b][r], c = pg.w1[b][r];
            float m = fmaxf(a, c);
            float ea = __expf(a - m), eb = __expf(c - m);
            be = ea / (ea + eb);
        }
        sbe[tid] = be;
    }
    __syncthreads();

    float4 r0v, r1v;
    uint4 rbv[2];
    auto loadT = [&](int k0) {
        int r = tid >> 2, c4 = tid & 3;
        int gr = row0 + r;
        r0v = make_float4(0.f, 0.f, 0.f, 0.f);
        r1v = r0v;
        if (gr < M) {
            r0v = *(const float4*)(Z0 + (size_t)gr * K + k0 + c4 * 4);
            r1v = *(const float4*)(Z1 + (size_t)gr * K + k0 + c4 * 4);
        }
#pragma unroll
        for (int j = 0; j < 2; j++) {
            int i = tid + j * 256;
            int k = i >> 5, c4b = i & 31;
            int gc = col0 + c4b * 4;
            rbv[j] = make_uint4(0, 0, 0, 0);
            if (gc < N) rbv[j] = *(const uint4*)(B + (size_t)(k0 + k) * N + gc);
        }
    };
    auto storeT = [&](int buf) {
        int r = tid >> 2, c4 = tid & 3;
        float be = sbe[r], ne = 1.f - be;
        uint4 u = make_uint4(f2tf(be * r0v.x + ne * r1v.x),
                             f2tf(be * r0v.y + ne * r1v.y),
                             f2tf(be * r0v.z + ne * r1v.z),
                             f2tf(be * r0v.w + ne * r1v.w));
        *(uint4*)&sA[buf][r * PA + c4 * 4] = u;
#pragma unroll
        for (int j = 0; j < 2; j++) {
            int i = tid + j * 256;
            int k = i >> 5, c4b = i & 31;
            *(uint4*)&sB[buf][k * PB + c4b * 4] = rbv[j];
        }
    };

    float acc[2][4][4];
#pragma unroll
    for (int i = 0; i < 2; i++)
#pragma unroll
        for (int j = 0; j < 4; j++)
#pragma unroll
            for (int q = 0; q < 4; q++) acc[i][j][q] = 0.f;

    unsigned sbaseA = (unsigned)__cvta_generic_to_shared(&sA[0][0]);
    const unsigned aLdm = ((wm * 32 + (lane & 15)) * PA + (lane >> 4) * 4) << 2;
    const int bB0 = (lane & 3) * PB + wn * 32 + (lane >> 2);

    loadT(0);
    storeT(0);
    __syncthreads();

    for (int t = 0; t < nk; t++) {
        int buf = t & 1;
        if (t + 1 < nk) loadT((t + 1) * 16);

#pragma unroll
        for (int ks = 0; ks < 2; ks++) {
            unsigned af[2][4];
            unsigned bf[4][2];
            unsigned aAddr = sbaseA + ((buf * 64 * PA) << 2) + aLdm + ((ks * 8) << 2);
#pragma unroll
            for (int mt = 0; mt < 2; mt++) {
                asm volatile("ldmatrix.sync.aligned.m8n8.x4.shared.b16 "
                             "{%0,%1,%2,%3}, [%4];"
                             : "=r"(af[mt][0]), "=r"(af[mt][1]),
                               "=r"(af[mt][2]), "=r"(af[mt][3])
                             : "r"(aAddr + ((mt * 16 * PA) << 2)));
            }
            const unsigned* bp = &sB[buf][bB0];
#pragma unroll
            for (int nt = 0; nt < 4; nt++) {
                const unsigned* p = bp + ks * 8 * PB + nt * 8;
                bf[nt][0] = p[0];
                bf[nt][1] = p[4 * PB];
            }
#pragma unroll
            for (int mt = 0; mt < 2; mt++)
#pragma unroll
                for (int nt = 0; nt < 4; nt++) {
                    asm volatile(
                        "mma.sync.aligned.m16n8k8.row.col.f32.tf32.tf32.f32 "
                        "{%0,%1,%2,%3}, {%4,%5,%6,%7}, {%8,%9}, {%0,%1,%2,%3};"
                        : "+f"(acc[mt][nt][0]), "+f"(acc[mt][nt][1]),
                          "+f"(acc[mt][nt][2]), "+f"(acc[mt][nt][3])
                        : "r"(af[mt][0]), "r"(af[mt][1]), "r"(af[mt][2]), "r"(af[mt][3]),
                          "r"(bf[nt][0]), "r"(bf[nt][1]));
                }
        }
        if (t + 1 < nk) storeT(buf ^ 1);
        __syncthreads();
    }

#pragma unroll
    for (int mt = 0; mt < 2; mt++) {
        int r0 = row0 + wm * 32 + mt * 16 + (lane >> 2);
#pragma unroll
        for (int nt = 0; nt < 4; nt++) {
            int c = col0 + wn * 32 + nt * 8 + (lane & 3) * 2;
            if (c < N) {
#pragma unroll
                for (int h = 0; h < 2; h++) {
                    int r = r0 + h * 8;
                    if (r < M) {
                        float v0 = acc[mt][nt][2 * h], v1 = acc[mt][nt][2 * h + 1];
                        *(float2*)(C + (size_t)r * N + c) = make_float2(v0, v1);
                        *(uint2*)(C2 + (size_t)r * N + c) =
                            make_uint2(f2tf(v0), f2tf(v1));
                    }
                }
            }
        }
    }
}

// ---------------- GAT kernels (grid.y = instance z) ----------------

__global__ void count_kernel(IP4 ed4) {
    int z = blockIdx.y;
    int i = blockIdx.x * blockDim.x + threadIdx.x;
    if (i >= NEDGE) return;
    atomicAdd(&G_CUR(z)[ed4.p[z][NEDGE + i]], 1);
}

__global__ void scan_kernel() {
    int z = blockIdx.x;
    int* cur = G_CUR(z);
    int* off = g_off[z];
    __shared__ int part[1024];
    int t = threadIdx.x;
    int base = t * 10;
    int v[10];
    int s = 0;
#pragma unroll
    for (int j = 0; j < 10; j++) {
        int idx = base + j;
        int c = (idx < NNODES) ? cur[idx] : 0;
        v[j] = c;
        s += c;
    }
    part[t] = s;
    __syncthreads();
    for (int o = 1; o < 1024; o <<= 1) {
        int x = (t >= o) ? part[t - o] : 0;
        __syncthreads();
        part[t] += x;
        __syncthreads();
    }
    int run = (t > 0) ? part[t - 1] : 0;
#pragma unroll
    for (int j = 0; j < 10; j++) {
        int idx = base + j;
        if (idx < NNODES) {
            off[idx] = run;
            cur[idx] = run;
            run += v[j];
        }
    }
    if (t == 0) off[NNODES] = NEDGE;
}

__global__ void scatter_kernel(IP4 ed4) {
    int z = blockIdx.y;
    int i = blockIdx.x * blockDim.x + threadIdx.x;
    if (i >= NEDGE) return;
    const int* ed = ed4.p[z];
    int d = ed[NEDGE + i];
    int p = atomicAdd(&G_CUR(z)[d], 1);
    g_eid[z][p] = ed[i];
}

// gather-aggregate with inline softmax exp + end normalization; bias+ELU fused.
// zbase selects the z-group (grid.y covers 2 instances per launch).
__global__ __launch_bounds__(256) void agg_kernel(FP4 bias4, int zbase) {
    int z = zbase + blockIdx.y;
    int wid = blockIdx.x * 8 + (threadIdx.x >> 5);
    if (wid >= NNODES * 4) return;
    const float* bias = bias4.p[z];
    const float* __restrict__ feat = g_feat[z];
    const float* __restrict__ el = G_EL(z);
    const int* __restrict__ eid = g_eid[z];
    int d = wid >> 2, strip = wid & 3;
    int lane = threadIdx.x & 31;
    int col = strip * 128 + lane * 4;
    int head = col >> 6;
    float erv = G_ER(z)[d * NHEAD + head];

    float4 acc = make_float4(0.f, 0.f, 0.f, 0.f);
    float sum_ax = 0.f;
    int b = g_off[z][d], e_ = g_off[z][d + 1];
    if (b < e_) {
        int sA = eid[b];
        int sB = (b + 1 < e_) ? eid[b + 1] : sA;
        float elA = el[sA * NHEAD + head];
        for (int i = b; i < e_; i++) {
            int sC = (i + 2 < e_) ? eid[i + 2] : sB;
            float elB = (i + 1 < e_) ? el[sB * NHEAD + head] : 0.f;
            float v = elA + erv;
            v = v > 0.f ? v : 0.2f * v;
            float ax = __expf(v);
            float4 f = *(const float4*)(feat + (size_t)sA * DDIM + col);
            acc.x += f.x * ax;
            acc.y += f.y * ax;
            acc.z += f.z * ax;
            acc.w += f.w * ax;
            sum_ax += ax;
            sA = sB; sB = sC; elA = elB;
        }
        float rcp = 1.f / sum_ax;
        acc.x *= rcp; acc.y *= rcp; acc.z *= rcp; acc.w *= rcp;
    }
    float4 bb = *(const float4*)(bias + col);
    float4 v;
    v.x = acc.x + bb.x; v.x = v.x > 0.f ? v.x : (__expf(v.x) - 1.f);
    v.y = acc.y + bb.y; v.y = v.y > 0.f ? v.y : (__expf(v.y) - 1.f);
    v.z = acc.z + bb.z; v.z = v.z > 0.f ? v.z : (__expf(v.z) - 1.f);
    v.w = acc.w + bb.w; v.w = v.w > 0.f ? v.w : (__expf(v.w) - 1.f);
    *(float4*)(g_z[z] + (size_t)d * DDIM + col) = v;
    *(uint4*)(&t_z[z][(size_t)d * DDIM + col]) =
        make_uint4(f2tf(v.x), f2tf(v.y), f2tf(v.z), f2tf(v.w));
}

// ---------------- host orchestration ----------------

extern "C" void kernel_launch(void* const* d_in, const int* in_sizes, int n_in,
                              void* d_out, int out_size) {
    // side streams + fork/join events (created once; capture-legal pattern)
    static cudaStream_t s_csr = nullptr, s_sem = nullptr;
    static cudaEvent_t ev_fork = nullptr, ev_join = nullptr;
    static cudaEvent_t ev_a01 = nullptr, ev_p0 = nullptr;
    if (!s_csr) {
        cudaStreamCreateWithFlags(&s_csr, cudaStreamNonBlocking);
        cudaStreamCreateWithFlags(&s_sem, cudaStreamNonBlocking);
        cudaEventCreateWithFlags(&ev_fork, cudaEventDisableTiming);
        cudaEventCreateWithFlags(&ev_join, cudaEventDisableTiming);
        cudaEventCreateWithFlags(&ev_a01, cudaEventDisableTiming);
        cudaEventCreateWithFlags(&ev_p0, cudaEventDisableTiming);
    }

    float *p_feat[4], *p_gz[4];
    unsigned *p_tx[2], *p_twhw[2], *p_tfc[2], *p_tpred[2], *p_tW1[2];
    unsigned *p_tW[4], *p_tz[4], *p_th[2];
    unsigned* p_zbuf;
    {
        float* base;
        cudaGetSymbolAddress((void**)&base, g_feat);
        for (int z = 0; z < 4; z++) p_feat[z] = base + (size_t)z * NNODES * DDIM;
        cudaGetSymbolAddress((void**)&base, g_z);
        for (int z = 0; z < 4; z++) p_gz[z] = base + (size_t)z * NNODES * DDIM;
        cudaGetSymbolAddress((void**)&p_zbuf, g_zbuf);
        unsigned* ub;
        cudaGetSymbolAddress((void**)&ub, t_x);
        for (int b = 0; b < 2; b++) p_tx[b] = ub + (size_t)b * NNODES * FDIM;
        cudaGetSymbolAddress((void**)&ub, t_whw);
        for (int b = 0; b < 2; b++) p_twhw[b] = ub + (size_t)b * FDIM * FDIM;
        cudaGetSymbolAddress((void**)&ub, t_fc);
        for (int b = 0; b < 2; b++) p_tfc[b] = ub + (size_t)b * 2 * FDIM * DDIM;
        cudaGetSymbolAddress((void**)&ub, t_pred);
        for (int b = 0; b < 2; b++) p_tpred[b] = ub + (size_t)b * DDIM * OSZ;
        cudaGetSymbolAddress((void**)&ub, t_W1);
        for (int b = 0; b < 2; b++) p_tW1[b] = ub + (size_t)b * DDIM * SEMH;
        cudaGetSymbolAddress((void**)&ub, t_W);
        for (int z = 0; z < 4; z++) p_tW[z] = ub + (size_t)z * FDIM * DDIM;
        cudaGetSymbolAddress((void**)&ub, t_z);
        for (int z = 0; z < 4; z++) p_tz[z] = ub + (size_t)z * NNODES * DDIM;
        cudaGetSymbolAddress((void**)&ub, t_h);
        for (int b = 0; b < 2; b++) p_th[b] = ub + (size_t)b * NNODES * OSZ;
    }
    float* p_el[4];
    float* p_er[4];
    float* p_w[4];
    for (int z = 0; z < 4; z++) {
        p_el[z] = (float*)p_zbuf + ZW_EL + (size_t)z * NNODES * NHEAD;
        p_er[z] = (float*)p_zbuf + ZW_ER + (size_t)z * NNODES * NHEAD;
        p_w[z]  = (float*)p_zbuf + ZW_W  + (size_t)z * NNODES;
    }

    const float* hx = (const float*)d_in[0];
    const float* tx = (const float*)d_in[1];
    const float* w_h[2]  = {(const float*)d_in[2],  (const float*)d_in[11]};
    const float* fc[2]   = {(const float*)d_in[3],  (const float*)d_in[12]};
    const float* al[2]   = {(const float*)d_in[4],  (const float*)d_in[13]};
    const float* ar[2]   = {(const float*)d_in[5],  (const float*)d_in[14]};
    const float* bias[2] = {(const float*)d_in[6],  (const float*)d_in[15]};
    const float* W1[2]   = {(const float*)d_in[7],  (const float*)d_in[16]};
    const float* b1[2]   = {(const float*)d_in[8],  (const float*)d_in[17]};
    const float* W2[2]   = {(const float*)d_in[9],  (const float*)d_in[18]};
    const float* pred[2] = {(const float*)d_in[10], (const float*)d_in[19]};

    IP4 ed4 = {{(const int*)d_in[20], (const int*)d_in[21],
                (const int*)d_in[22], (const int*)d_in[23]}};
    FP4 bias4 = {{bias[0], bias[0] + DDIM, bias[1], bias[1] + DDIM}};

    float* out  = (float*)d_out;
    float* h1   = out;
    float* h2   = out + (size_t)NNODES * OSZ;
    float* prod = out + (size_t)2 * NNODES * OSZ;

    const int SM_NN4 = 4 * (128 * 20 + 16 * 136) * 4;   // 75776
    const int SM_NT  = 4 * (128 * 20 + 128 * 20) * 4;   // 81920
    cudaFuncSetAttribute(mma_gemm_async<4, false, 1>,
                         cudaFuncAttributeMaxDynamicSharedMemorySize, SM_NN4);
    cudaFuncSetAttribute(mma_gemm_async<4, false, 4>,
                         cudaFuncAttributeMaxDynamicSharedMemorySize, SM_NN4);
    cudaFuncSetAttribute(mma_gemm_async<4, false, 5>,
                         cudaFuncAttributeMaxDynamicSharedMemorySize, SM_NN4);
    cudaFuncSetAttribute(mma_gemm_async<4, true, 3>,
                         cudaFuncAttributeMaxDynamicSharedMemorySize, SM_NT);

    // 0) clear accumulators; FORK CSR build; cvt + W + feat on main
    cudaMemsetAsync(p_zbuf, 0, ZW_TOT * sizeof(unsigned), 0);
    cudaEventRecord(ev_fork, 0);
    cudaStreamWaitEvent(s_csr, ev_fork, 0);
    count_kernel<<<dim3((NEDGE + 255) / 256, 4), 256, 0, s_csr>>>(ed4);
    scan_kernel<<<4, 1024, 0, s_csr>>>();
    scatter_kernel<<<dim3((NEDGE + 255) / 256, 4), 256, 0, s_csr>>>(ed4);
    cudaEventRecord(ev_join, s_csr);

    {
        CVT c = {};
        c.src[0] = hx;      c.dst[0] = p_tx[0];    c.n4[0] = NNODES * FDIM / 4;
        c.src[1] = tx;      c.dst[1] = p_tx[1];    c.n4[1] = NNODES * FDIM / 4;
        c.src[2] = w_h[0];  c.dst[2] = p_twhw[0];  c.n4[2] = FDIM * FDIM / 4;
        c.src[3] = w_h[1];  c.dst[3] = p_twhw[1];  c.n4[3] = FDIM * FDIM / 4;
        c.src[4] = fc[0];   c.dst[4] = p_tfc[0];   c.n4[4] = 2 * FDIM * DDIM / 4;
        c.src[5] = fc[1];   c.dst[5] = p_tfc[1];   c.n4[5] = 2 * FDIM * DDIM / 4;
        c.src[6] = pred[0]; c.dst[6] = p_tpred[0]; c.n4[6] = DDIM * OSZ / 4;
        c.src[7] = pred[1]; c.dst[7] = p_tpred[1]; c.n4[7] = DDIM * OSZ / 4;
        c.src[8] = W1[0];   c.dst[8] = p_tW1[0];   c.n4[8] = DDIM * SEMH / 4;
        c.src[9] = W1[1];   c.dst[9] = p_tW1[1];   c.n4[9] = DDIM * SEMH / 4;
        cvt_kernel<<<dim3(640, 10), 256>>>(c);
    }

    // 1) combined weights W[z] = w_h[b] @ fc[b][m]
    {
        GB gb = {};
        for (int z = 0; z < 4; z++) {
            gb.A[z] = p_twhw[z >> 1];
            gb.B[z] = p_tfc[z >> 1] + (size_t)(z & 1) * FDIM * DDIM;
            gb.C[z] = p_tW[z];
        }
        dim3 g(DDIM / 128, FDIM / 128, 4);
        mma_gemm_async<4, false, 1><<<g, 256, SM_NN4>>>(gb, FDIM, DDIM, FDIM);
    }
    // 2) feat = x @ W  (batched x4, fused el/er epilogue)
    {
        GB gb = {};
        for (int z = 0; z < 4; z++) {
            gb.A[z] = p_tx[z >> 1];
            gb.B[z] = p_tW[z];
            gb.C[z] = p_feat[z];
            gb.AL[z] = (z & 2) ? (al[1] + (z & 1) * NHEAD * 64) : (al[0] + (z & 1) * NHEAD * 64);
            gb.AR[z] = (z & 2) ? (ar[1] + (z & 1) * NHEAD * 64) : (ar[0] + (z & 1) * NHEAD * 64);
            gb.EL[z] = p_el[z];
            gb.ER[z] = p_er[z];
        }
        dim3 g(DDIM / 128, (NNODES + 127) / 128, 4);
        mma_gemm_async<4, false, 4><<<g, 256, SM_NN4>>>(gb, NNODES, DDIM, FDIM);
    }

    // JOIN CSR; then pipeline z-groups:
    //   main: agg(z01) -> agg(z23) -> sem(z23) -> pred(b1)
    //   s_sem: after agg(z01): sem(z01) -> pred(b0)
    cudaStreamWaitEvent(0, ev_join, 0);
    agg_kernel<<<dim3((NNODES * 4 + 7) / 8, 2), 256>>>(bias4, 0);
    cudaEventRecord(ev_a01, 0);

    cudaStreamWaitEvent(s_sem, ev_a01, 0);
    {
        GB gb = {};
        for (int q = 0; q < 2; q++) {
            int z = q;  // z = 0,1  (branch 0)
            gb.A[q] = p_tz[z];
            gb.B[q] = p_tW1[0];
            gb.B1[q] = b1[0];
            gb.W2p[q] = W2[0];
            gb.WO[q] = p_w[z];
        }
        dim3 g(1, (NNODES + 127) / 128, 2);
        mma_gemm_async<4, false, 5><<<g, 256, SM_NN4, s_sem>>>(gb, NNODES, SEMH, DDIM);
    }
    {
        PG pg = {};
        pg.z0[0] = p_gz[0]; pg.z1[0] = p_gz[1];
        pg.w0[0] = p_w[0];  pg.w1[0] = p_w[1];
        pg.B[0]  = p_tpred[0];
        pg.C[0]  = h1;
        pg.C2[0] = p_th[0];
        dim3 g(1, (NNODES + 63) / 64, 1);
        pred_fused_kernel<<<g, 256, 0, s_sem>>>(pg, NNODES, OSZ, DDIM);
    }
    cudaEventRecord(ev_p0, s_sem);

    agg_kernel<<<dim3((NNODES * 4 + 7) / 8, 2), 256>>>(bias4, 2);
    {
        GB gb = {};
        for (int q = 0; q < 2; q++) {
            int z = 2 + q;  // z = 2,3  (branch 1)
            gb.A[q] = p_tz[z];
            gb.B[q] = p_tW1[1];
            gb.B1[q] = b1[1];
            gb.W2p[q] = W2[1];
            gb.WO[q] = p_w[z];
        }
        dim3 g(1, (NNODES + 127) / 128, 2);
        mma_gemm_async<4, false, 5><<<g, 256, SM_NN4>>>(gb, NNODES, SEMH, DDIM);
    }
    {
        PG pg = {};
        pg.z0[0] = p_gz[2]; pg.z1[0] = p_gz[3];
        pg.w0[0] = p_w[2];  pg.w1[0] = p_w[3];
        pg.B[0]  = p_tpred[1];
        pg.C[0]  = h2;
        pg.C2[0] = p_th[1];
        dim3 g(1, (NNODES + 63) / 64, 1);
        pred_fused_kernel<<<g, 256>>>(pg, NNODES, OSZ, DDIM);
    }

    // join pred(b0) before the final NT GEMM
    cudaStreamWaitEvent(0, ev_p0, 0);

    // 6) prod = h1 @ h2^T (tf32 copies, streaming stores, ldmatrix A+B)
    {
        GB gb = {};
        gb.A[0] = p_th[0]; gb.B[0] = p_th[1]; gb.C[0] = prod;
        dim3 g((NNODES + 127) / 128, (NNODES + 127) / 128, 1);
        mma_gemm_async<4, true, 3><<<g, 256, SM_NT>>>(gb, NNODES, NNODES, OSZ);
    }
}